// round 12
// baseline (speedup 1.0000x reference)
#include <cuda_runtime.h>
#include <stdint.h>
#include <math.h>

#define Pw    7
#define PP    49
#define HEADS 8
#define DH    32
#define INNER 256
#define Cc    128
#define Bb    32
#define HW    56
#define WINS  2048
#define MROWS (WINS*PP)    // 100352

static __device__ float g_xw  [(size_t)MROWS * Cc];
static __device__ float g_omid[(size_t)MROWS * INNER];
static __device__ float g_wqkv_t[768 * 128];
static __device__ float g_wout_t[256 * 128];
static __device__ float g_mask [4 * 49 * 56];
static __device__ float g_attn_dump[(size_t)WINS * HEADS * PP * PP];
static __device__ float g_o_dump  [(size_t)Bb * Cc * HW * HW];

__device__ __forceinline__ unsigned int f2tf32(float f) {
    unsigned int u; asm("cvt.rna.tf32.f32 %0, %1;" : "=r"(u) : "f"(f)); return u;
}
__device__ __forceinline__ float tf32r(float f) { return __uint_as_float(f2tf32(f)); }

__device__ __forceinline__ void mma_tf32(float c[4],
    unsigned int a0, unsigned int a1, unsigned int a2, unsigned int a3,
    unsigned int b0, unsigned int b1)
{
    asm volatile(
        "mma.sync.aligned.m16n8k8.row.col.f32.tf32.tf32.f32 "
        "{%0,%1,%2,%3}, {%4,%5,%6,%7}, {%8,%9}, {%0,%1,%2,%3};"
        : "+f"(c[0]), "+f"(c[1]), "+f"(c[2]), "+f"(c[3])
        : "r"(a0), "r"(a1), "r"(a2), "r"(a3), "r"(b0), "r"(b1));
}

__device__ __forceinline__ void cp16(unsigned int saddr, const void* gaddr) {
    asm volatile("cp.async.cg.shared.global [%0], [%1], 16;" :: "r"(saddr), "l"(gaddr));
}
__device__ __forceinline__ void cp_commit() { asm volatile("cp.async.commit_group;"); }
__device__ __forceinline__ void cp_wait1()  { asm volatile("cp.async.wait_group 1;"); }
__device__ __forceinline__ void cp_wait0()  { asm volatile("cp.async.wait_group 0;"); }

// ---------------------------------------------------------------------------
// Kernel 0: transpose + tf32-round weights, precompute bias+mask tables.
// ---------------------------------------------------------------------------
__global__ void prep_wm(const float* __restrict__ wq, const float* __restrict__ wo,
                        const float* __restrict__ pos)
{
    int idx = blockIdx.x * 256 + threadIdx.x;
    if (idx < 768 * 128) {
        int k = idx / 768, n = idx - k * 768;
        g_wqkv_t[idx] = tf32r(wq[n * 128 + k]);
    }
    int i2 = idx - 768 * 128;
    if (i2 >= 0 && i2 < 256 * 128) {
        int k = i2 / 128, n = i2 - k * 128;
        g_wout_t[i2] = tf32r(wo[n * 256 + k]);
    }
    if (idx < 4 * 49 * 56) {
        int cls = idx / (49 * 56);
        int rem = idx - cls * 49 * 56;
        int i = rem / 56, j = rem - i * 56;
        float val;
        if (j >= 49) {
            val = -1e30f;
        } else {
            int xi = i / Pw, yi = i - xi * Pw;
            int xj = j / Pw, yj = j - xj * Pw;
            val = pos[(xj - xi + 6) * 13 + (yj - yi + 6)];
            if ((cls & 1) && ((i >= 28) != (j >= 28))) val = -1e30f;
            if ((cls & 2) && ((yi >= 4) != (yj >= 4))) val = -1e30f;
        }
        g_mask[idx] = val;
    }
}

// ---------------------------------------------------------------------------
// Kernel 1: gather (roll -3,-3 + window partition) -> g_xw, tf32-rounded.
// ---------------------------------------------------------------------------
__global__ void gather_x(const float* __restrict__ x)
{
    __shared__ float sm[128][65];
    const int b  = blockIdx.x / 49;
    const int p0 = (blockIdx.x - b * 49) * 64;
    const int tid = threadIdx.x;

    for (int i = tid; i < 128 * 64; i += 256) {
        int c = i >> 6, p = i & 63;
        sm[c][p] = x[((size_t)b * 128 + c) * 3136 + p0 + p];
    }
    __syncthreads();
    for (int i = tid; i < 64 * 128; i += 256) {
        int p = i >> 7, c = i & 127;
        int pix = p0 + p;
        int h = pix / HW, w = pix - h * HW;
        int hs = h - 3; if (hs < 0) hs += HW;
        int ws = w - 3; if (ws < 0) ws += HW;
        int win = b * 64 + (hs / Pw) * 8 + (ws / Pw);
        int t   = (hs % Pw) * Pw + (ws % Pw);
        g_xw[((size_t)win * PP + t) * Cc + c] = tf32r(sm[c][p]);
    }
}

// ---------------------------------------------------------------------------
// Kernel 2: FUSED per-(window,head) QKV projection + TC attention.
// 16384 blocks x 128 threads.  Projection: M=49(pad64), N=96 (q|k|v), K=128,
// weights cp.async double-buffered from L2. Then the proven R11 attention.
// ---------------------------------------------------------------------------
#define XS(r,c)     xsm[(r) * 132 + (c)]
#define WS(st,k,n)  wsm[(st) * 1664 + (k) * 104 + (n)]
#define QS(r,c)     qsm[(r) * 36 + (c)]
#define KS(r,c)     ksm[(r) * 40 + (c)]
#define VS(r,c)     vsm[(r) * 40 + (c)]
#define SS(r,c)     xsm[(r) * 60 + (c)]    // alias: xsm dead after projection

__global__ void __launch_bounds__(128, 3) fused_qkv_attn(float* __restrict__ attn_out)
{
    __shared__ float xsm[49 * 132];
    __shared__ float wsm[2 * 16 * 104];
    __shared__ float qsm[49 * 36];
    __shared__ float ksm[56 * 40];
    __shared__ float vsm[56 * 40];

    const int blk  = blockIdx.x;
    const int win  = blk >> 3;
    const int head = blk & 7;
    const int wl   = win & 63;
    const int cls  = ((wl >= 56) ? 1 : 0) | (((wl == 55) || (wl == 63)) ? 2 : 0);

    const int tid  = threadIdx.x;
    const int lane = tid & 31;
    const int warp = tid >> 5;
    const int wm   = warp * 16;
    const int qr   = lane >> 2;
    const int ql   = lane & 3;

    // zero pad rows 49..55 of k/v
    for (int idx = tid; idx < 7 * 40; idx += 128) {
        ksm[(49 + idx / 40) * 40 + idx % 40] = 0.f;
        vsm[(49 + idx / 40) * 40 + idx % 40] = 0.f;
    }

    // load xw window tile (coalesced float4)
    const float* xb = g_xw + (size_t)win * PP * Cc;
    for (int idx = tid; idx < PP * 32; idx += 128) {
        int j = idx >> 5, f = (idx & 31) * 4;
        *(float4*)&XS(j, f) = *(const float4*)(xb + j * 128 + f);
    }

    // weight-slice cp.async setup: thread -> (row, f4), 3 strips (q,k,v)
    const int wrow = tid >> 3;
    const int wf4  = (tid & 7) * 4;
    const unsigned int wbase = (unsigned int)__cvta_generic_to_shared(wsm);
    const float* wg = g_wqkv_t + (size_t)wrow * 768 + head * 32 + wf4;

    // prologue: chunk 0 -> stage 0
    #pragma unroll
    for (int s3 = 0; s3 < 3; s3++)
        cp16(wbase + (unsigned)(wrow * 104 + s3 * 32 + wf4) * 4, wg + s3 * 256);
    cp_commit();

    const int rA = wm + qr, rB = rA + 8;
    const bool vA = (rA < PP), vB = (rB < PP);

    float acc[12][4];
    #pragma unroll
    for (int nt = 0; nt < 12; nt++)
        #pragma unroll
        for (int c = 0; c < 4; c++) acc[nt][c] = 0.f;

    // ---- projection GEMM: 8 k-chunks of 16 ----
    #pragma unroll
    for (int kc = 0; kc < 8; kc++) {
        if (kc < 7) {
            const int snew = (kc + 1) & 1;
            const float* wgc = wg + (size_t)(kc + 1) * 16 * 768;
            #pragma unroll
            for (int s3 = 0; s3 < 3; s3++)
                cp16(wbase + (unsigned)(snew * 1664 + wrow * 104 + s3 * 32 + wf4) * 4,
                     wgc + s3 * 256);
            cp_commit();
            cp_wait1();
        } else {
            cp_wait0();
        }
        __syncthreads();
        const int st = kc & 1;
        #pragma unroll
        for (int k8 = 0; k8 < 16; k8 += 8) {
            const int kk = k8 + ql;
            const int gk = kc * 16 + kk;
            unsigned int a[4], b[12][2];
            a[0] = vA ? __float_as_uint(XS(rA, gk))     : 0u;
            a[1] = vB ? __float_as_uint(XS(rB, gk))     : 0u;
            a[2] = vA ? __float_as_uint(XS(rA, gk + 4)) : 0u;
            a[3] = vB ? __float_as_uint(XS(rB, gk + 4)) : 0u;
            #pragma unroll
            for (int nt = 0; nt < 12; nt++) {
                int c = nt * 8 + qr;
                b[nt][0] = __float_as_uint(WS(st, kk, c));
                b[nt][1] = __float_as_uint(WS(st, kk + 4, c));
            }
            #pragma unroll
            for (int nt = 0; nt < 12; nt++)
                mma_tf32(acc[nt], a[0], a[1], a[2], a[3], b[nt][0], b[nt][1]);
        }
        __syncthreads();
    }

    // ---- fragment epilogue -> qsm (scaled) / ksm / vsm, tf32-rounded ----
    const float scale = 0.1767766952966369f;  // 32^-0.5 folded into q
    #pragma unroll
    for (int nt = 0; nt < 4; nt++) {
        int c = nt * 8 + ql * 2;
        if (vA) *(float2*)&QS(rA, c) =
            make_float2(tf32r(acc[nt][0] * scale), tf32r(acc[nt][1] * scale));
        if (vB) *(float2*)&QS(rB, c) =
            make_float2(tf32r(acc[nt][2] * scale), tf32r(acc[nt][3] * scale));
    }
    #pragma unroll
    for (int nt = 4; nt < 8; nt++) {
        int c = (nt - 4) * 8 + ql * 2;
        if (vA) *(float2*)&KS(rA, c) =
            make_float2(tf32r(acc[nt][0]), tf32r(acc[nt][1]));
        if (vB) *(float2*)&KS(rB, c) =
            make_float2(tf32r(acc[nt][2]), tf32r(acc[nt][3]));
    }
    #pragma unroll
    for (int nt = 8; nt < 12; nt++) {
        int c = (nt - 8) * 8 + ql * 2;
        if (vA) *(float2*)&VS(rA, c) =
            make_float2(tf32r(acc[nt][0]), tf32r(acc[nt][1]));
        if (vB) *(float2*)&VS(rB, c) =
            make_float2(tf32r(acc[nt][2]), tf32r(acc[nt][3]));
    }
    __syncthreads();   // projection done; xsm free for SS alias

    // ---- S = (Q*scale) @ K^T + mask (accumulators init from table) ----
    const float* mrowA = g_mask + cls * (49 * 56) + (vA ? rA : 48) * 56;
    const float* mrowB = g_mask + cls * (49 * 56) + (vB ? rB : 48) * 56;
    float s[7][4];
    #pragma unroll
    for (int nt = 0; nt < 7; nt++) {
        const int j0 = nt * 8 + ql * 2;
        float2 ma = *(const float2*)(mrowA + j0);
        float2 mb = *(const float2*)(mrowB + j0);
        s[nt][0] = ma.x; s[nt][1] = ma.y;
        s[nt][2] = mb.x; s[nt][3] = mb.y;
    }

    #pragma unroll
    for (int ks = 0; ks < 4; ks++) {
        const int kk = ks * 8 + ql;
        unsigned int a[4], b[7][2];
        a[0] = vA ? __float_as_uint(QS(rA, kk))     : 0u;
        a[1] = vB ? __float_as_uint(QS(rB, kk))     : 0u;
        a[2] = vA ? __float_as_uint(QS(rA, kk + 4)) : 0u;
        a[3] = vB ? __float_as_uint(QS(rB, kk + 4)) : 0u;
        #pragma unroll
        for (int nt = 0; nt < 7; nt++) {
            int c = nt * 8 + qr;
            b[nt][0] = __float_as_uint(KS(c, kk));
            b[nt][1] = __float_as_uint(KS(c, kk + 4));
        }
        #pragma unroll
        for (int nt = 0; nt < 7; nt++)
            mma_tf32(s[nt], a[0], a[1], a[2], a[3], b[nt][0], b[nt][1]);
    }

    // ---- softmax on fragments ----
    {
        float mA = -1e30f, mB = -1e30f;
        #pragma unroll
        for (int nt = 0; nt < 7; nt++) {
            mA = fmaxf(mA, fmaxf(s[nt][0], s[nt][1]));
            mB = fmaxf(mB, fmaxf(s[nt][2], s[nt][3]));
        }
        mA = fmaxf(mA, __shfl_xor_sync(0xffffffffu, mA, 1));
        mA = fmaxf(mA, __shfl_xor_sync(0xffffffffu, mA, 2));
        mB = fmaxf(mB, __shfl_xor_sync(0xffffffffu, mB, 1));
        mB = fmaxf(mB, __shfl_xor_sync(0xffffffffu, mB, 2));

        float sA = 0.f, sB = 0.f;
        #pragma unroll
        for (int nt = 0; nt < 7; nt++) {
            s[nt][0] = __expf(s[nt][0] - mA);
            s[nt][1] = __expf(s[nt][1] - mA);
            s[nt][2] = __expf(s[nt][2] - mB);
            s[nt][3] = __expf(s[nt][3] - mB);
            sA += s[nt][0] + s[nt][1];
            sB += s[nt][2] + s[nt][3];
        }
        sA += __shfl_xor_sync(0xffffffffu, sA, 1);
        sA += __shfl_xor_sync(0xffffffffu, sA, 2);
        sB += __shfl_xor_sync(0xffffffffu, sB, 1);
        sB += __shfl_xor_sync(0xffffffffu, sB, 2);
        const float iAu = 1.0f / sA, iBu = 1.0f / sB;

        #pragma unroll
        for (int nt = 0; nt < 7; nt++) {
            int j0 = nt * 8 + ql * 2;
            if (vA) *(float2*)&SS(rA, j0) = make_float2(s[nt][0] * iAu, s[nt][1] * iAu);
            if (vB) *(float2*)&SS(rB, j0) = make_float2(s[nt][2] * iBu, s[nt][3] * iBu);
        }
    }
    __syncthreads();

    // coalesced attn write (fp32)
    float* aout = attn_out + (size_t)blk * PP * PP;
    for (int idx = tid; idx < PP * PP; idx += 128) {
        int r = idx / PP;
        aout[idx] = SS(r, idx - r * PP);
    }

    // ---- O = P @ V ----
    float o[4][4];
    #pragma unroll
    for (int nt = 0; nt < 4; nt++)
        #pragma unroll
        for (int c = 0; c < 4; c++) o[nt][c] = 0.f;

    #pragma unroll
    for (int ks = 0; ks < 7; ks++) {
        const int kk = ks * 8 + ql;
        unsigned int a[4], b[4][2];
        a[0] = vA ? f2tf32(SS(rA, kk))     : 0u;
        a[1] = vB ? f2tf32(SS(rB, kk))     : 0u;
        a[2] = vA ? f2tf32(SS(rA, kk + 4)) : 0u;
        a[3] = vB ? f2tf32(SS(rB, kk + 4)) : 0u;
        #pragma unroll
        for (int nt = 0; nt < 4; nt++) {
            int c = nt * 8 + qr;
            b[nt][0] = __float_as_uint(VS(kk, c));
            b[nt][1] = __float_as_uint(VS(kk + 4, c));
        }
        #pragma unroll
        for (int nt = 0; nt < 4; nt++)
            mma_tf32(o[nt], a[0], a[1], a[2], a[3], b[nt][0], b[nt][1]);
    }

    float* ob = g_omid + (size_t)win * PP * INNER + head * 32;
    #pragma unroll
    for (int nt = 0; nt < 4; nt++) {
        int c = nt * 8 + ql * 2;
        if (vA)
            *(float2*)&ob[(size_t)rA * INNER + c] =
                make_float2(tf32r(o[nt][0]), tf32r(o[nt][1]));
        if (vB)
            *(float2*)&ob[(size_t)rB * INNER + c] =
                make_float2(tf32r(o[nt][2]), tf32r(o[nt][3]));
    }
}

// ---------------------------------------------------------------------------
// Kernel 3: out GEMM, tf32 TC, 3-stage cp.async + bias; smem-staged result,
// w-fastest coalesced scatter (unchanged from R10).
// ---------------------------------------------------------------------------
#define OA(st,r,k)  smbuf[(st) * 2560 + (r) * 20 + (k)]
#define OB(st,k,n)  smbuf[7680 + (st) * 2176 + (k) * 136 + (n)]
#define OSTG(r,c)   smbuf[(r) * 133 + (c)]

__global__ void out_gemm_tc(const float* __restrict__ b_out,
                            float* __restrict__ out)
{
    __shared__ float smbuf[17024];
    const unsigned int A_STRIDE = 2560 * 4;
    const unsigned int B_STRIDE = 2176 * 4;

    const int tid  = threadIdx.x;
    const int bm   = blockIdx.y * 128;
    const int lane = tid & 31, wid = tid >> 5;
    const int wm   = (wid & 1) * 64, wn = (wid >> 1) * 32;

    const int ar = tid & 127, ak = (tid >> 7) * 4;
    const float* agp = g_omid + (size_t)(bm + ar) * INNER + ak;
    const int bk = tid >> 4, bn8 = (tid & 15) * 8;
    const float* bgp = g_wout_t + (size_t)bk * 128 + bn8;

    unsigned int sA = (unsigned int)__cvta_generic_to_shared(&OA(0, ar, ak));
    unsigned int sB = (unsigned int)__cvta_generic_to_shared(&OB(0, bk, bn8));

    float acc[4][4][4];
    #pragma unroll
    for (int i = 0; i < 4; i++)
        #pragma unroll
        for (int j = 0; j < 4; j++)
            #pragma unroll
            for (int c = 0; c < 4; c++) acc[i][j][c] = 0.f;

    #pragma unroll
    for (int s = 0; s < 2; s++) {
        const int k0 = s * 16;
        cp16(sA + s * A_STRIDE,      agp + k0);
        cp16(sA + s * A_STRIDE + 32, agp + k0 + 8);
        cp16(sB + s * B_STRIDE,      bgp + (size_t)k0 * 128);
        cp16(sB + s * B_STRIDE + 16, bgp + (size_t)k0 * 128 + 4);
        cp_commit();
    }

    #pragma unroll
    for (int ks = 0; ks < 16; ks++) {
        if (ks < 15) cp_wait1(); else cp_wait0();
        __syncthreads();
        const int st = ks % 3;
        #pragma unroll
        for (int k8 = 0; k8 < 16; k8 += 8) {
            unsigned int af[4][4], bf[4][2];
            const int kk = k8 + (lane & 3);
            #pragma unroll
            for (int mt = 0; mt < 4; mt++) {
                int r = wm + mt * 16 + (lane >> 2);
                af[mt][0] = __float_as_uint(OA(st, r, kk));
                af[mt][1] = __float_as_uint(OA(st, r + 8, kk));
                af[mt][2] = __float_as_uint(OA(st, r, kk + 4));
                af[mt][3] = __float_as_uint(OA(st, r + 8, kk + 4));
            }
            #pragma unroll
            for (int nt = 0; nt < 4; nt++) {
                int c = wn + nt * 8 + (lane >> 2);
                bf[nt][0] = __float_as_uint(OB(st, kk, c));
                bf[nt][1] = __float_as_uint(OB(st, kk + 4, c));
            }
            #pragma unroll
            for (int mt = 0; mt < 4; mt++)
                #pragma unroll
                for (int nt = 0; nt < 4; nt++)
                    mma_tf32(acc[mt][nt], af[mt][0], af[mt][1], af[mt][2], af[mt][3],
                             bf[nt][0], bf[nt][1]);
        }
        __syncthreads();
        if (ks + 2 < 16) {
            const int snew = (ks + 2) % 3;
            const int k0 = (ks + 2) * 16;
            cp16(sA + snew * A_STRIDE,      agp + k0);
            cp16(sA + snew * A_STRIDE + 32, agp + k0 + 8);
            cp16(sB + snew * B_STRIDE,      bgp + (size_t)k0 * 128);
            cp16(sB + snew * B_STRIDE + 16, bgp + (size_t)k0 * 128 + 4);
            cp_commit();
        }
    }

    __syncthreads();
    #pragma unroll
    for (int mt = 0; mt < 4; mt++) {
        #pragma unroll
        for (int half = 0; half < 2; half++) {
            int r = wm + mt * 16 + (lane >> 2) + half * 8;
            #pragma unroll
            for (int nt = 0; nt < 4; nt++) {
                int c = wn + nt * 8 + (lane & 3) * 2;
                OSTG(r, c)     = acc[mt][nt][half * 2 + 0] + b_out[c];
                OSTG(r, c + 1) = acc[mt][nt][half * 2 + 1] + b_out[c + 1];
            }
        }
    }
    __syncthreads();

    for (int idx = tid; idx < 128 * 128; idx += 256) {
        int c  = idx >> 7;
        int sr = idx & 127;
        int r  = bm + sr;
        int win = r / PP;
        int t   = r - win * PP;
        int b   = win >> 6;
        int wl  = win & 63;
        int i1  = wl >> 3, i2 = wl & 7;
        int xx  = t / Pw,  yy = t - (t / Pw) * Pw;
        int h = i1 * Pw + xx + 3; if (h >= HW) h -= HW;
        int w = i2 * Pw + yy + 3; if (w >= HW) w -= HW;
        out[((size_t)b * 128 + c) * 3136 + h * HW + w] = OSTG(sr, c);
    }
}

// ---------------------------------------------------------------------------
extern "C" void kernel_launch(void* const* d_in, const int* in_sizes, int n_in,
                              void* d_out, int out_size)
{
    const float* x      = (const float*)d_in[0];
    const float* w_qkv  = (const float*)d_in[1];
    const float* w_out  = (const float*)d_in[2];
    const float* b_out  = (const float*)d_in[3];
    const float* pos    = (const float*)d_in[4];

    const long long O_ELEMS = (long long)Bb * Cc * HW * HW;
    const long long A_ELEMS = (long long)WINS * HEADS * PP * PP;

    float* outp = (float*)d_out;
    float* o_ptr;
    float* attn_ptr;

    if ((long long)out_size >= O_ELEMS + A_ELEMS) {
        o_ptr    = outp;
        attn_ptr = outp + O_ELEMS;
    } else if ((long long)out_size == A_ELEMS) {
        attn_ptr = outp;
        cudaGetSymbolAddress((void**)&o_ptr, g_o_dump);
    } else {
        o_ptr = outp;
        cudaGetSymbolAddress((void**)&attn_ptr, g_attn_dump);
    }

    prep_wm<<<512, 256>>>(w_qkv, w_out, pos);
    gather_x<<<Bb * 49, 256>>>(x);
    fused_qkv_attn<<<WINS * HEADS, 128>>>(attn_ptr);
    out_gemm_tc<<<dim3(1, MROWS / 128), 256>>>(b_out, o_ptr);
}

// round 13
// speedup vs baseline: 1.1873x; 1.1873x over previous
#include <cuda_runtime.h>
#include <stdint.h>
#include <math.h>

#define Pw    7
#define PP    49
#define HEADS 8
#define DH    32
#define INNER 256
#define Cc    128
#define Bb    32
#define HW    56
#define WINS  2048
#define MROWS (WINS*PP)    // 100352

static __device__ float g_xw  [(size_t)MROWS * Cc];
static __device__ float g_qkv [(size_t)MROWS * 3 * INNER];
static __device__ float g_omid[(size_t)MROWS * INNER];
static __device__ float g_wqkv_t[768 * 128];
static __device__ float g_wout_t[256 * 128];
static __device__ float g_mask [4 * 49 * 56];
static __device__ float g_attn_dump[(size_t)WINS * HEADS * PP * PP];
static __device__ float g_o_dump  [(size_t)Bb * Cc * HW * HW];

__device__ __forceinline__ unsigned int f2tf32(float f) {
    unsigned int u; asm("cvt.rna.tf32.f32 %0, %1;" : "=r"(u) : "f"(f)); return u;
}
__device__ __forceinline__ float tf32r(float f) { return __uint_as_float(f2tf32(f)); }

__device__ __forceinline__ void mma_tf32(float c[4],
    unsigned int a0, unsigned int a1, unsigned int a2, unsigned int a3,
    unsigned int b0, unsigned int b1)
{
    asm volatile(
        "mma.sync.aligned.m16n8k8.row.col.f32.tf32.tf32.f32 "
        "{%0,%1,%2,%3}, {%4,%5,%6,%7}, {%8,%9}, {%0,%1,%2,%3};"
        : "+f"(c[0]), "+f"(c[1]), "+f"(c[2]), "+f"(c[3])
        : "r"(a0), "r"(a1), "r"(a2), "r"(a3), "r"(b0), "r"(b1));
}

__device__ __forceinline__ void cp16(unsigned int saddr, const void* gaddr) {
    asm volatile("cp.async.cg.shared.global [%0], [%1], 16;" :: "r"(saddr), "l"(gaddr));
}
__device__ __forceinline__ void cp_commit() { asm volatile("cp.async.commit_group;"); }
__device__ __forceinline__ void cp_wait1()  { asm volatile("cp.async.wait_group 1;"); }
__device__ __forceinline__ void cp_wait0()  { asm volatile("cp.async.wait_group 0;"); }

__device__ __forceinline__ float4 tf32r4(float4 v) {
    return make_float4(tf32r(v.x), tf32r(v.y), tf32r(v.z), tf32r(v.w));
}
__device__ __forceinline__ float4 tf32r4s(float4 v, float s) {
    return make_float4(tf32r(v.x * s), tf32r(v.y * s), tf32r(v.z * s), tf32r(v.w * s));
}

// ---------------------------------------------------------------------------
// Kernel 0: transpose + tf32-round weights, precompute bias+mask tables.
// ---------------------------------------------------------------------------
__global__ void prep_wm(const float* __restrict__ wq, const float* __restrict__ wo,
                        const float* __restrict__ pos)
{
    int idx = blockIdx.x * 256 + threadIdx.x;
    if (idx < 768 * 128) {
        int k = idx / 768, n = idx - k * 768;
        g_wqkv_t[idx] = tf32r(wq[n * 128 + k]);
    }
    int i2 = idx - 768 * 128;
    if (i2 >= 0 && i2 < 256 * 128) {
        int k = i2 / 128, n = i2 - k * 128;
        g_wout_t[i2] = tf32r(wo[n * 256 + k]);
    }
    if (idx < 4 * 49 * 56) {
        int cls = idx / (49 * 56);
        int rem = idx - cls * 49 * 56;
        int i = rem / 56, j = rem - i * 56;
        float val;
        if (j >= 49) {
            val = -1e30f;
        } else {
            int xi = i / Pw, yi = i - xi * Pw;
            int xj = j / Pw, yj = j - xj * Pw;
            val = pos[(xj - xi + 6) * 13 + (yj - yi + 6)];
            if ((cls & 1) && ((i >= 28) != (j >= 28))) val = -1e30f;
            if ((cls & 2) && ((yi >= 4) != (yj >= 4))) val = -1e30f;
        }
        g_mask[idx] = val;
    }
}

// ---------------------------------------------------------------------------
// Kernel 1: gather (roll -3,-3 + window partition) -> g_xw, tf32-rounded.
// ---------------------------------------------------------------------------
__global__ void gather_x(const float* __restrict__ x)
{
    __shared__ float sm[128][65];
    const int b  = blockIdx.x / 49;
    const int p0 = (blockIdx.x - b * 49) * 64;
    const int tid = threadIdx.x;

    for (int i = tid; i < 128 * 64; i += 256) {
        int c = i >> 6, p = i & 63;
        sm[c][p] = x[((size_t)b * 128 + c) * 3136 + p0 + p];
    }
    __syncthreads();
    for (int i = tid; i < 64 * 128; i += 256) {
        int p = i >> 7, c = i & 127;
        int pix = p0 + p;
        int h = pix / HW, w = pix - h * HW;
        int hs = h - 3; if (hs < 0) hs += HW;
        int ws = w - 3; if (ws < 0) ws += HW;
        int win = b * 64 + (hs / Pw) * 8 + (ws / Pw);
        int t   = (hs % Pw) * Pw + (ws % Pw);
        g_xw[((size_t)win * PP + t) * Cc + c] = tf32r(sm[c][p]);
    }
}

// ---------------------------------------------------------------------------
// Kernel 2: QKV GEMM, tf32 TC, 3-stage cp.async, 512 threads, warp 32x32.
// M=100352, N=768, K=128. Block 128x128, 16 warps (4m x 4n).
// ---------------------------------------------------------------------------
__global__ void __launch_bounds__(512, 2) qkv_gemm_tc()
{
    __shared__ float As[3][128][20];
    __shared__ float Bs[3][16][136];
    const unsigned int A_STRIDE = 128 * 20 * 4;
    const unsigned int B_STRIDE = 16 * 136 * 4;

    const int tid  = threadIdx.x;
    const int bm   = blockIdx.y * 128;
    const int bn   = blockIdx.x * 128;
    const int lane = tid & 31, wid = tid >> 5;
    const int wm   = (wid & 3) * 32, wn = (wid >> 2) * 32;
    const int qr   = lane >> 2, ql = lane & 3;

    const int ar = tid & 127, ak = (tid >> 7) * 4;       // 1 cp16/thread
    const float* agp = g_xw + (size_t)(bm + ar) * Cc + ak;
    const int bk = tid >> 5, bn4 = (tid & 31) * 4;       // 1 cp16/thread
    const float* bgp = g_wqkv_t + (size_t)bk * 768 + bn + bn4;

    unsigned int sA = (unsigned int)__cvta_generic_to_shared(&As[0][ar][ak]);
    unsigned int sB = (unsigned int)__cvta_generic_to_shared(&Bs[0][bk][bn4]);

    float acc[2][4][4];
    #pragma unroll
    for (int i = 0; i < 2; i++)
        #pragma unroll
        for (int j = 0; j < 4; j++)
            #pragma unroll
            for (int c = 0; c < 4; c++) acc[i][j][c] = 0.f;

    #pragma unroll
    for (int s = 0; s < 2; s++) {
        const int k0 = s * 16;
        cp16(sA + s * A_STRIDE, agp + k0);
        cp16(sB + s * B_STRIDE, bgp + (size_t)k0 * 768);
        cp_commit();
    }

    #pragma unroll
    for (int ks = 0; ks < 8; ks++) {
        if (ks < 7) cp_wait1(); else cp_wait0();
        __syncthreads();
        const int st = ks % 3;
        #pragma unroll
        for (int k8 = 0; k8 < 16; k8 += 8) {
            unsigned int af[2][4], bf[4][2];
            const int kk = k8 + ql;
            #pragma unroll
            for (int mt = 0; mt < 2; mt++) {
                int r = wm + mt * 16 + qr;
                af[mt][0] = __float_as_uint(As[st][r][kk]);
                af[mt][1] = __float_as_uint(As[st][r + 8][kk]);
                af[mt][2] = __float_as_uint(As[st][r][kk + 4]);
                af[mt][3] = __float_as_uint(As[st][r + 8][kk + 4]);
            }
            #pragma unroll
            for (int nt = 0; nt < 4; nt++) {
                int c = wn + nt * 8 + qr;
                bf[nt][0] = __float_as_uint(Bs[st][kk][c]);
                bf[nt][1] = __float_as_uint(Bs[st][kk + 4][c]);
            }
            #pragma unroll
            for (int mt = 0; mt < 2; mt++)
                #pragma unroll
                for (int nt = 0; nt < 4; nt++)
                    mma_tf32(acc[mt][nt], af[mt][0], af[mt][1], af[mt][2], af[mt][3],
                             bf[nt][0], bf[nt][1]);
        }
        __syncthreads();
        if (ks + 2 < 8) {
            const int snew = (ks + 2) % 3;
            const int k0 = (ks + 2) * 16;
            cp16(sA + snew * A_STRIDE, agp + k0);
            cp16(sB + snew * B_STRIDE, bgp + (size_t)k0 * 768);
            cp_commit();
        }
    }

    #pragma unroll
    for (int mt = 0; mt < 2; mt++) {
        int r0 = bm + wm + mt * 16 + qr;
        #pragma unroll
        for (int nt = 0; nt < 4; nt++) {
            int c = bn + wn + nt * 8 + ql * 2;
            *(float2*)&g_qkv[(size_t)r0 * 768 + c] =
                make_float2(acc[mt][nt][0], acc[mt][nt][1]);
            *(float2*)&g_qkv[(size_t)(r0 + 8) * 768 + c] =
                make_float2(acc[mt][nt][2], acc[mt][nt][3]);
        }
    }
}

// ---------------------------------------------------------------------------
// Kernel 3: TC attention (R11 best: mask-table init, scale folded into Q).
// ---------------------------------------------------------------------------
#define QSM(r,c) usm[(r) * 36 + (c)]
#define SSM(r,c) usm[(r) * 60 + (c)]

__global__ void __launch_bounds__(128, 7) attn_tc_kernel(float* __restrict__ attn_out)
{
    const int blk  = blockIdx.x;
    const int win  = blk >> 3;
    const int head = blk & 7;
    const int wl   = win & 63;
    const int cls  = ((wl >= 56) ? 1 : 0) | (((wl == 55) || (wl == 63)) ? 2 : 0);

    __shared__ float usm[49 * 60];
    __shared__ float ksm[56][40];
    __shared__ float vsm[56][40];

    const int tid  = threadIdx.x;
    const int lane = tid & 31;
    const int warp = tid >> 5;
    const int wm   = warp * 16;
    const int qr   = lane >> 2;
    const int ql   = lane & 3;

    const float* qb = g_qkv + (size_t)win * PP * 768 + head * 32;
    const float scale = 0.1767766952966369f;

    for (int idx = tid; idx < 7 * 40; idx += 128) {
        ksm[49 + idx / 40][idx % 40] = 0.f;
        vsm[49 + idx / 40][idx % 40] = 0.f;
    }

    for (int idx = tid; idx < PP * 8; idx += 128) {
        const int j = idx >> 3, f = (idx & 7) * 4;
        const float* row = qb + (size_t)j * 768 + f;
        float4 qv = *(const float4*)(row);
        float4 kv = *(const float4*)(row + 256);
        float4 vv = *(const float4*)(row + 512);
        *(float4*)&QSM(j, f) = tf32r4s(qv, scale);
        *(float4*)&ksm[j][f] = tf32r4(kv);
        *(float4*)&vsm[j][f] = tf32r4(vv);
    }

    const int rA = wm + qr, rB = rA + 8;
    const bool vA = (rA < PP), vB = (rB < PP);

    const float* mrowA = g_mask + cls * (49 * 56) + (vA ? rA : 48) * 56;
    const float* mrowB = g_mask + cls * (49 * 56) + (vB ? rB : 48) * 56;
    float s[7][4];
    #pragma unroll
    for (int nt = 0; nt < 7; nt++) {
        const int j0 = nt * 8 + ql * 2;
        float2 ma = *(const float2*)(mrowA + j0);
        float2 mb = *(const float2*)(mrowB + j0);
        s[nt][0] = ma.x; s[nt][1] = ma.y;
        s[nt][2] = mb.x; s[nt][3] = mb.y;
    }
    __syncthreads();

    #pragma unroll
    for (int ks = 0; ks < 4; ks++) {
        const int kk = ks * 8 + ql;
        unsigned int a[4], b[7][2];
        a[0] = vA ? __float_as_uint(QSM(rA, kk))     : 0u;
        a[1] = vB ? __float_as_uint(QSM(rB, kk))     : 0u;
        a[2] = vA ? __float_as_uint(QSM(rA, kk + 4)) : 0u;
        a[3] = vB ? __float_as_uint(QSM(rB, kk + 4)) : 0u;
        #pragma unroll
        for (int nt = 0; nt < 7; nt++) {
            int c = nt * 8 + qr;
            b[nt][0] = __float_as_uint(ksm[c][kk]);
            b[nt][1] = __float_as_uint(ksm[c][kk + 4]);
        }
        #pragma unroll
        for (int nt = 0; nt < 7; nt++)
            mma_tf32(s[nt], a[0], a[1], a[2], a[3], b[nt][0], b[nt][1]);
    }

    __syncthreads();

    {
        float mA = -1e30f, mB = -1e30f;
        #pragma unroll
        for (int nt = 0; nt < 7; nt++) {
            mA = fmaxf(mA, fmaxf(s[nt][0], s[nt][1]));
            mB = fmaxf(mB, fmaxf(s[nt][2], s[nt][3]));
        }
        mA = fmaxf(mA, __shfl_xor_sync(0xffffffffu, mA, 1));
        mA = fmaxf(mA, __shfl_xor_sync(0xffffffffu, mA, 2));
        mB = fmaxf(mB, __shfl_xor_sync(0xffffffffu, mB, 1));
        mB = fmaxf(mB, __shfl_xor_sync(0xffffffffu, mB, 2));

        float sA = 0.f, sB = 0.f;
        #pragma unroll
        for (int nt = 0; nt < 7; nt++) {
            s[nt][0] = __expf(s[nt][0] - mA);
            s[nt][1] = __expf(s[nt][1] - mA);
            s[nt][2] = __expf(s[nt][2] - mB);
            s[nt][3] = __expf(s[nt][3] - mB);
            sA += s[nt][0] + s[nt][1];
            sB += s[nt][2] + s[nt][3];
        }
        sA += __shfl_xor_sync(0xffffffffu, sA, 1);
        sA += __shfl_xor_sync(0xffffffffu, sA, 2);
        sB += __shfl_xor_sync(0xffffffffu, sB, 1);
        sB += __shfl_xor_sync(0xffffffffu, sB, 2);
        const float iAu = 1.0f / sA, iBu = 1.0f / sB;

        #pragma unroll
        for (int nt = 0; nt < 7; nt++) {
            int j0 = nt * 8 + ql * 2;
            if (vA) *(float2*)&SSM(rA, j0) = make_float2(s[nt][0] * iAu, s[nt][1] * iAu);
            if (vB) *(float2*)&SSM(rB, j0) = make_float2(s[nt][2] * iBu, s[nt][3] * iBu);
        }
    }
    __syncthreads();

    float* aout = attn_out + (size_t)blk * PP * PP;
    for (int idx = tid; idx < PP * PP; idx += 128) {
        int r = idx / PP;
        aout[idx] = SSM(r, idx - r * PP);
    }

    float o[4][4];
    #pragma unroll
    for (int nt = 0; nt < 4; nt++)
        #pragma unroll
        for (int c = 0; c < 4; c++) o[nt][c] = 0.f;

    #pragma unroll
    for (int ks = 0; ks < 7; ks++) {
        const int kk = ks * 8 + ql;
        unsigned int a[4], b[4][2];
        a[0] = vA ? f2tf32(SSM(rA, kk))     : 0u;
        a[1] = vB ? f2tf32(SSM(rB, kk))     : 0u;
        a[2] = vA ? f2tf32(SSM(rA, kk + 4)) : 0u;
        a[3] = vB ? f2tf32(SSM(rB, kk + 4)) : 0u;
        #pragma unroll
        for (int nt = 0; nt < 4; nt++) {
            int c = nt * 8 + qr;
            b[nt][0] = __float_as_uint(vsm[kk][c]);
            b[nt][1] = __float_as_uint(vsm[kk + 4][c]);
        }
        #pragma unroll
        for (int nt = 0; nt < 4; nt++)
            mma_tf32(o[nt], a[0], a[1], a[2], a[3], b[nt][0], b[nt][1]);
    }

    float* ob = g_omid + (size_t)win * PP * INNER + head * 32;
    #pragma unroll
    for (int nt = 0; nt < 4; nt++) {
        int c = nt * 8 + ql * 2;
        if (vA)
            *(float2*)&ob[(size_t)rA * INNER + c] =
                make_float2(tf32r(o[nt][0]), tf32r(o[nt][1]));
        if (vB)
            *(float2*)&ob[(size_t)rB * INNER + c] =
                make_float2(tf32r(o[nt][2]), tf32r(o[nt][3]));
    }
}

// ---------------------------------------------------------------------------
// Kernel 4: out GEMM, 512 threads, warp 32x32, 3-stage cp.async + staged
// coalesced scatter. M=100352, N=128, K=256.
// ---------------------------------------------------------------------------
#define OA(st,r,k)  smbuf[(st) * 2560 + (r) * 20 + (k)]
#define OB(st,k,n)  smbuf[7680 + (st) * 2176 + (k) * 136 + (n)]
#define OSTG(r,c)   smbuf[(r) * 133 + (c)]

__global__ void __launch_bounds__(512, 2) out_gemm_tc(const float* __restrict__ b_out,
                                                      float* __restrict__ out)
{
    __shared__ float smbuf[17024];
    const unsigned int A_STRIDE = 2560 * 4;
    const unsigned int B_STRIDE = 2176 * 4;

    const int tid  = threadIdx.x;
    const int bm   = blockIdx.y * 128;
    const int lane = tid & 31, wid = tid >> 5;
    const int wm   = (wid & 3) * 32, wn = (wid >> 2) * 32;
    const int qr   = lane >> 2, ql = lane & 3;

    const int ar = tid & 127, ak = (tid >> 7) * 4;
    const float* agp = g_omid + (size_t)(bm + ar) * INNER + ak;
    const int bk = tid >> 5, bn4 = (tid & 31) * 4;
    const float* bgp = g_wout_t + (size_t)bk * 128 + bn4;

    unsigned int sA = (unsigned int)__cvta_generic_to_shared(&OA(0, ar, ak));
    unsigned int sB = (unsigned int)__cvta_generic_to_shared(&OB(0, bk, bn4));

    float acc[2][4][4];
    #pragma unroll
    for (int i = 0; i < 2; i++)
        #pragma unroll
        for (int j = 0; j < 4; j++)
            #pragma unroll
            for (int c = 0; c < 4; c++) acc[i][j][c] = 0.f;

    #pragma unroll
    for (int s = 0; s < 2; s++) {
        const int k0 = s * 16;
        cp16(sA + s * A_STRIDE, agp + k0);
        cp16(sB + s * B_STRIDE, bgp + (size_t)k0 * 128);
        cp_commit();
    }

    #pragma unroll
    for (int ks = 0; ks < 16; ks++) {
        if (ks < 15) cp_wait1(); else cp_wait0();
        __syncthreads();
        const int st = ks % 3;
        #pragma unroll
        for (int k8 = 0; k8 < 16; k8 += 8) {
            unsigned int af[2][4], bf[4][2];
            const int kk = k8 + ql;
            #pragma unroll
            for (int mt = 0; mt < 2; mt++) {
                int r = wm + mt * 16 + qr;
                af[mt][0] = __float_as_uint(OA(st, r, kk));
                af[mt][1] = __float_as_uint(OA(st, r + 8, kk));
                af[mt][2] = __float_as_uint(OA(st, r, kk + 4));
                af[mt][3] = __float_as_uint(OA(st, r + 8, kk + 4));
            }
            #pragma unroll
            for (int nt = 0; nt < 4; nt++) {
                int c = wn + nt * 8 + qr;
                bf[nt][0] = __float_as_uint(OB(st, kk, c));
                bf[nt][1] = __float_as_uint(OB(st, kk + 4, c));
            }
            #pragma unroll
            for (int mt = 0; mt < 2; mt++)
                #pragma unroll
                for (int nt = 0; nt < 4; nt++)
                    mma_tf32(acc[mt][nt], af[mt][0], af[mt][1], af[mt][2], af[mt][3],
                             bf[nt][0], bf[nt][1]);
        }
        __syncthreads();
        if (ks + 2 < 16) {
            const int snew = (ks + 2) % 3;
            const int k0 = (ks + 2) * 16;
            cp16(sA + snew * A_STRIDE, agp + k0);
            cp16(sB + snew * B_STRIDE, bgp + (size_t)k0 * 128);
            cp_commit();
        }
    }

    __syncthreads();
    #pragma unroll
    for (int mt = 0; mt < 2; mt++) {
        #pragma unroll
        for (int half = 0; half < 2; half++) {
            int r = wm + mt * 16 + qr + half * 8;
            #pragma unroll
            for (int nt = 0; nt < 4; nt++) {
                int c = wn + nt * 8 + ql * 2;
                OSTG(r, c)     = acc[mt][nt][half * 2 + 0] + b_out[c];
                OSTG(r, c + 1) = acc[mt][nt][half * 2 + 1] + b_out[c + 1];
            }
        }
    }
    __syncthreads();

    for (int idx = tid; idx < 128 * 128; idx += 512) {
        int c  = idx >> 7;
        int sr = idx & 127;
        int r  = bm + sr;
        int win = r / PP;
        int t   = r - win * PP;
        int b   = win >> 6;
        int wl  = win & 63;
        int i1  = wl >> 3, i2 = wl & 7;
        int xx  = t / Pw,  yy = t - (t / Pw) * Pw;
        int h = i1 * Pw + xx + 3; if (h >= HW) h -= HW;
        int w = i2 * Pw + yy + 3; if (w >= HW) w -= HW;
        out[((size_t)b * 128 + c) * 3136 + h * HW + w] = OSTG(sr, c);
    }
}

// ---------------------------------------------------------------------------
extern "C" void kernel_launch(void* const* d_in, const int* in_sizes, int n_in,
                              void* d_out, int out_size)
{
    const float* x      = (const float*)d_in[0];
    const float* w_qkv  = (const float*)d_in[1];
    const float* w_out  = (const float*)d_in[2];
    const float* b_out  = (const float*)d_in[3];
    const float* pos    = (const float*)d_in[4];

    const long long O_ELEMS = (long long)Bb * Cc * HW * HW;
    const long long A_ELEMS = (long long)WINS * HEADS * PP * PP;

    float* outp = (float*)d_out;
    float* o_ptr;
    float* attn_ptr;

    if ((long long)out_size >= O_ELEMS + A_ELEMS) {
        o_ptr    = outp;
        attn_ptr = outp + O_ELEMS;
    } else if ((long long)out_size == A_ELEMS) {
        attn_ptr = outp;
        cudaGetSymbolAddress((void**)&o_ptr, g_o_dump);
    } else {
        o_ptr = outp;
        cudaGetSymbolAddress((void**)&attn_ptr, g_attn_dump);
    }

    prep_wm<<<512, 256>>>(w_qkv, w_out, pos);
    gather_x<<<Bb * 49, 256>>>(x);
    qkv_gemm_tc<<<dim3(768 / 128, MROWS / 128), 512>>>();
    attn_tc_kernel<<<WINS * HEADS, 128>>>(attn_ptr);
    out_gemm_tc<<<dim3(1, MROWS / 128), 512>>>(b_out, o_ptr);
}

// round 15
// speedup vs baseline: 1.3182x; 1.1103x over previous
#include <cuda_runtime.h>
#include <stdint.h>
#include <math.h>

#define Pw    7
#define PP    49
#define HEADS 8
#define DH    32
#define INNER 256
#define Cc    128
#define Bb    32
#define HW    56
#define WINS  2048
#define MROWS (WINS*PP)    // 100352

static __device__ float g_xw  [(size_t)MROWS * Cc];
static __device__ float g_qkv [(size_t)MROWS * 3 * INNER];
static __device__ float g_omid[(size_t)MROWS * INNER];
static __device__ float g_wqkv_r[768 * 128];   // [n][k] original layout, tf32-rounded
static __device__ float g_wout_r[128 * 256];   // [n][k] original layout, tf32-rounded
static __device__ float g_mask [4 * 49 * 56];
static __device__ float g_attn_dump[(size_t)WINS * HEADS * PP * PP];
static __device__ float g_o_dump  [(size_t)Bb * Cc * HW * HW];

__device__ __forceinline__ unsigned int f2tf32(float f) {
    unsigned int u; asm("cvt.rna.tf32.f32 %0, %1;" : "=r"(u) : "f"(f)); return u;
}
__device__ __forceinline__ float tf32r(float f) { return __uint_as_float(f2tf32(f)); }

__device__ __forceinline__ void mma_tf32(float c[4],
    unsigned int a0, unsigned int a1, unsigned int a2, unsigned int a3,
    unsigned int b0, unsigned int b1)
{
    asm volatile(
        "mma.sync.aligned.m16n8k8.row.col.f32.tf32.tf32.f32 "
        "{%0,%1,%2,%3}, {%4,%5,%6,%7}, {%8,%9}, {%0,%1,%2,%3};"
        : "+f"(c[0]), "+f"(c[1]), "+f"(c[2]), "+f"(c[3])
        : "r"(a0), "r"(a1), "r"(a2), "r"(a3), "r"(b0), "r"(b1));
}

__device__ __forceinline__ void ldsm4(unsigned int& r0, unsigned int& r1,
                                      unsigned int& r2, unsigned int& r3,
                                      unsigned int addr)
{
    asm volatile("ldmatrix.sync.aligned.m8n8.x4.shared.b16 {%0,%1,%2,%3}, [%4];"
        : "=r"(r0), "=r"(r1), "=r"(r2), "=r"(r3) : "r"(addr));
}
__device__ __forceinline__ void ldsm2(unsigned int& r0, unsigned int& r1,
                                      unsigned int addr)
{
    asm volatile("ldmatrix.sync.aligned.m8n8.x2.shared.b16 {%0,%1}, [%2];"
        : "=r"(r0), "=r"(r1) : "r"(addr));
}

__device__ __forceinline__ void cp16(unsigned int saddr, const void* gaddr) {
    asm volatile("cp.async.cg.shared.global [%0], [%1], 16;" :: "r"(saddr), "l"(gaddr));
}
__device__ __forceinline__ void cp_commit() { asm volatile("cp.async.commit_group;"); }
__device__ __forceinline__ void cp_wait1()  { asm volatile("cp.async.wait_group 1;"); }
__device__ __forceinline__ void cp_wait0()  { asm volatile("cp.async.wait_group 0;"); }

__device__ __forceinline__ float4 tf32r4(float4 v) {
    return make_float4(tf32r(v.x), tf32r(v.y), tf32r(v.z), tf32r(v.w));
}
__device__ __forceinline__ float4 tf32r4s(float4 v, float s) {
    return make_float4(tf32r(v.x * s), tf32r(v.y * s), tf32r(v.z * s), tf32r(v.w * s));
}

// ---------------------------------------------------------------------------
// Kernel 0: tf32-round weights (original [n][k] layout) + bias+mask tables.
// ---------------------------------------------------------------------------
__global__ void prep_wm(const float* __restrict__ wq, const float* __restrict__ wo,
                        const float* __restrict__ pos)
{
    int idx = blockIdx.x * 256 + threadIdx.x;
    if (idx < 768 * 128) g_wqkv_r[idx] = tf32r(wq[idx]);
    int i2 = idx - 768 * 128;
    if (i2 >= 0 && i2 < 128 * 256) g_wout_r[i2] = tf32r(wo[i2]);
    if (idx < 4 * 49 * 56) {
        int cls = idx / (49 * 56);
        int rem = idx - cls * 49 * 56;
        int i = rem / 56, j = rem - i * 56;
        float val;
        if (j >= 49) {
            val = -1e30f;
        } else {
            int xi = i / Pw, yi = i - xi * Pw;
            int xj = j / Pw, yj = j - xj * Pw;
            val = pos[(xj - xi + 6) * 13 + (yj - yi + 6)];
            if ((cls & 1) && ((i >= 28) != (j >= 28))) val = -1e30f;
            if ((cls & 2) && ((yi >= 4) != (yj >= 4))) val = -1e30f;
        }
        g_mask[idx] = val;
    }
}

// ---------------------------------------------------------------------------
// Kernel 1: gather (roll -3,-3 + window partition) -> g_xw, tf32-rounded.
// ---------------------------------------------------------------------------
__global__ void gather_x(const float* __restrict__ x)
{
    __shared__ float sm[128][65];
    const int b  = blockIdx.x / 49;
    const int p0 = (blockIdx.x - b * 49) * 64;
    const int tid = threadIdx.x;

    for (int i = tid; i < 128 * 64; i += 256) {
        int c = i >> 6, p = i & 63;
        sm[c][p] = x[((size_t)b * 128 + c) * 3136 + p0 + p];
    }
    __syncthreads();
    for (int i = tid; i < 64 * 128; i += 256) {
        int p = i >> 7, c = i & 127;
        int pix = p0 + p;
        int h = pix / HW, w = pix - h * HW;
        int hs = h - 3; if (hs < 0) hs += HW;
        int ws = w - 3; if (ws < 0) ws += HW;
        int win = b * 64 + (hs / Pw) * 8 + (ws / Pw);
        int t   = (hs % Pw) * Pw + (ws % Pw);
        g_xw[((size_t)win * PP + t) * Cc + c] = tf32r(sm[c][p]);
    }
}

// ---------------------------------------------------------------------------
// Kernel 2: QKV GEMM, ldmatrix fragments, 3-stage cp.async, 512 thr.
// M=100352, N=768, K=128. Block 128x128, 16 warps (4m x 4n), warp 32x32.
// A smem [m][k] stride 20; B smem [n][k] stride 20 (direct w_qkv layout).
// ---------------------------------------------------------------------------
__global__ void __launch_bounds__(512, 2) qkv_gemm_tc()
{
    __shared__ float As[3][128][20];
    __shared__ float Bs[3][128][20];
    const unsigned int STG = 2560 * 4;   // bytes per stage

    const int tid  = threadIdx.x;
    const int bm   = blockIdx.y * 128;
    const int bn   = blockIdx.x * 128;
    const int lane = tid & 31, wid = tid >> 5;
    const int wm   = (wid & 3) * 32, wn = (wid >> 2) * 32;
    const int qr   = lane >> 2, ql = lane & 3;

    const int fr = tid >> 2, fq = (tid & 3) * 4;       // fill: 1 cp16/thread each
    const float* agp = g_xw     + (size_t)(bm + fr) * 128 + fq;
    const float* bgp = g_wqkv_r + (size_t)(bn + fr) * 128 + fq;

    const unsigned int aSm = (unsigned int)__cvta_generic_to_shared(&As[0][fr][fq]);
    const unsigned int bSm = (unsigned int)__cvta_generic_to_shared(&Bs[0][fr][fq]);
    const unsigned int aBase = (unsigned int)__cvta_generic_to_shared(As);
    const unsigned int bBase = (unsigned int)__cvta_generic_to_shared(Bs);

    // ldmatrix source addresses (absolute = xBase + off)
    const unsigned int aoff = ((wm + (lane & 15)) * 20 + 4 * (lane >> 4)) * 4;
    const unsigned int boff = (((lane & 7) + 8 * (lane >> 4) + wn) * 20
                               + 4 * ((lane >> 3) & 1)) * 4;

    float acc[2][4][4];
    #pragma unroll
    for (int i = 0; i < 2; i++)
        #pragma unroll
        for (int j = 0; j < 4; j++)
            #pragma unroll
            for (int c = 0; c < 4; c++) acc[i][j][c] = 0.f;

    #pragma unroll
    for (int s = 0; s < 2; s++) {
        const int k0 = s * 16;
        cp16(aSm + s * STG, agp + k0);
        cp16(bSm + s * STG, bgp + k0);
        cp_commit();
    }

    #pragma unroll
    for (int ks = 0; ks < 8; ks++) {
        if (ks < 7) cp_wait1(); else cp_wait0();
        __syncthreads();
        const int st = ks % 3;
        #pragma unroll
        for (int k8 = 0; k8 < 16; k8 += 8) {
            unsigned int af[2][4], bf[4][2];
            ldsm4(af[0][0], af[0][1], af[0][2], af[0][3],
                  aBase + st * STG + aoff + k8 * 4);
            ldsm4(af[1][0], af[1][1], af[1][2], af[1][3],
                  aBase + st * STG + aoff + (320 + k8) * 4);
            ldsm4(bf[0][0], bf[0][1], bf[1][0], bf[1][1],
                  bBase + st * STG + boff + k8 * 4);
            ldsm4(bf[2][0], bf[2][1], bf[3][0], bf[3][1],
                  bBase + st * STG + boff + (320 + k8) * 4);
            #pragma unroll
            for (int mt = 0; mt < 2; mt++)
                #pragma unroll
                for (int nt = 0; nt < 4; nt++)
                    mma_tf32(acc[mt][nt], af[mt][0], af[mt][1], af[mt][2], af[mt][3],
                             bf[nt][0], bf[nt][1]);
        }
        __syncthreads();
        if (ks + 2 < 8) {
            const int snew = (ks + 2) % 3;
            const int k0 = (ks + 2) * 16;
            cp16(aSm + snew * STG, agp + k0);
            cp16(bSm + snew * STG, bgp + k0);
            cp_commit();
        }
    }

    #pragma unroll
    for (int mt = 0; mt < 2; mt++) {
        int r0 = bm + wm + mt * 16 + qr;
        #pragma unroll
        for (int nt = 0; nt < 4; nt++) {
            int c = bn + wn + nt * 8 + ql * 2;
            *(float2*)&g_qkv[(size_t)r0 * 768 + c] =
                make_float2(acc[mt][nt][0], acc[mt][nt][1]);
            *(float2*)&g_qkv[(size_t)(r0 + 8) * 768 + c] =
                make_float2(acc[mt][nt][2], acc[mt][nt][3]);
        }
    }
}

// ---------------------------------------------------------------------------
// Kernel 3: TC attention with ldmatrix fragments.
// usm: Q [49][36] then P [49][60] (union). ksm [56][36]. vsm transposed [32][60].
// ---------------------------------------------------------------------------
#define QSM(r,c) usm[(r) * 36 + (c)]
#define SSM(r,c) usm[(r) * 60 + (c)]

__global__ void __launch_bounds__(128, 7) attn_tc_kernel(float* __restrict__ attn_out)
{
    const int blk  = blockIdx.x;
    const int win  = blk >> 3;
    const int head = blk & 7;
    const int wl   = win & 63;
    const int cls  = ((wl >= 56) ? 1 : 0) | (((wl == 55) || (wl == 63)) ? 2 : 0);

    __shared__ float usm[49 * 60];     // Q then P
    __shared__ float ksm[56 * 36];     // K [j][d]
    __shared__ float vsm[32 * 60];     // V^T [d][j]

    const int tid  = threadIdx.x;
    const int lane = tid & 31;
    const int warp = tid >> 5;
    const int wm   = warp * 16;
    const int qr   = lane >> 2;
    const int ql   = lane & 3;

    const float* qb = g_qkv + (size_t)win * PP * 768 + head * 32;
    const float scale = 0.1767766952966369f;

    // zero pads: Q rows 49..63 (ldmatrix reads them), ksm rows 49..55, vsm cols 49..59
    for (int idx = tid; idx < 15 * 36; idx += 128)
        QSM(49 + idx / 36, idx % 36) = 0.f;
    for (int idx = tid; idx < 7 * 32; idx += 128)
        ksm[(49 + (idx >> 5)) * 36 + (idx & 31)] = 0.f;
    for (int idx = tid; idx < 32 * 11; idx += 128)
        vsm[(idx / 11) * 60 + 49 + (idx % 11)] = 0.f;

    // fused float4 load of q/k/v rows (Q pre-scaled; V stored transposed)
    for (int idx = tid; idx < PP * 8; idx += 128) {
        const int j = idx >> 3, f = (idx & 7) * 4;
        const float* row = qb + (size_t)j * 768 + f;
        float4 qv = *(const float4*)(row);
        float4 kv = *(const float4*)(row + 256);
        float4 vv = *(const float4*)(row + 512);
        *(float4*)&QSM(j, f)       = tf32r4s(qv, scale);
        *(float4*)&ksm[j * 36 + f] = tf32r4(kv);
        vsm[(f + 0) * 60 + j] = tf32r(vv.x);
        vsm[(f + 1) * 60 + j] = tf32r(vv.y);
        vsm[(f + 2) * 60 + j] = tf32r(vv.z);
        vsm[(f + 3) * 60 + j] = tf32r(vv.w);
    }

    const int rA = wm + qr, rB = rA + 8;
    const bool vA = (rA < PP), vB = (rB < PP);

    // init S accumulators from mask table
    const float* mrowA = g_mask + cls * (49 * 56) + (vA ? rA : 48) * 56;
    const float* mrowB = g_mask + cls * (49 * 56) + (vB ? rB : 48) * 56;
    float s[7][4];
    #pragma unroll
    for (int nt = 0; nt < 7; nt++) {
        const int j0 = nt * 8 + ql * 2;
        float2 ma = *(const float2*)(mrowA + j0);
        float2 mb = *(const float2*)(mrowB + j0);
        s[nt][0] = ma.x; s[nt][1] = ma.y;
        s[nt][2] = mb.x; s[nt][3] = mb.y;
    }
    __syncthreads();

    const unsigned int usmB = (unsigned int)__cvta_generic_to_shared(usm);
    const unsigned int ksmB = (unsigned int)__cvta_generic_to_shared(ksm);
    const unsigned int vsmB = (unsigned int)__cvta_generic_to_shared(vsm);

    // ---- S = (Q*scale) @ K^T + mask ----
    const unsigned int qaoff = ((wm + (lane & 15)) * 36 + 4 * (lane >> 4)) * 4;
    const unsigned int kboff  = (((lane & 7) + 8 * (lane >> 4)) * 36
                                 + 4 * ((lane >> 3) & 1)) * 4;
    const unsigned int kboff2 = ((lane & 7) * 36 + 4 * ((lane >> 3) & 1)) * 4;

    #pragma unroll
    for (int ks = 0; ks < 4; ks++) {
        const int k8 = ks * 8;
        unsigned int a[4], b[7][2];
        ldsm4(a[0], a[1], a[2], a[3], usmB + qaoff + k8 * 4);
        ldsm4(b[0][0], b[0][1], b[1][0], b[1][1], ksmB + kboff  + (k8) * 4);
        ldsm4(b[2][0], b[2][1], b[3][0], b[3][1], ksmB + kboff  + (16 * 36 + k8) * 4);
        ldsm4(b[4][0], b[4][1], b[5][0], b[5][1], ksmB + kboff  + (32 * 36 + k8) * 4);
        ldsm2(b[6][0], b[6][1],                   ksmB + kboff2 + (48 * 36 + k8) * 4);
        #pragma unroll
        for (int nt = 0; nt < 7; nt++)
            mma_tf32(s[nt], a[0], a[1], a[2], a[3], b[nt][0], b[nt][1]);
    }

    __syncthreads();   // Q reads done; usm becomes P storage

    // ---- softmax on fragments ----
    {
        float mA = -1e30f, mB = -1e30f;
        #pragma unroll
        for (int nt = 0; nt < 7; nt++) {
            mA = fmaxf(mA, fmaxf(s[nt][0], s[nt][1]));
            mB = fmaxf(mB, fmaxf(s[nt][2], s[nt][3]));
        }
        mA = fmaxf(mA, __shfl_xor_sync(0xffffffffu, mA, 1));
        mA = fmaxf(mA, __shfl_xor_sync(0xffffffffu, mA, 2));
        mB = fmaxf(mB, __shfl_xor_sync(0xffffffffu, mB, 1));
        mB = fmaxf(mB, __shfl_xor_sync(0xffffffffu, mB, 2));

        float sA = 0.f, sB = 0.f;
        #pragma unroll
        for (int nt = 0; nt < 7; nt++) {
            s[nt][0] = __expf(s[nt][0] - mA);
            s[nt][1] = __expf(s[nt][1] - mA);
            s[nt][2] = __expf(s[nt][2] - mB);
            s[nt][3] = __expf(s[nt][3] - mB);
            sA += s[nt][0] + s[nt][1];
            sB += s[nt][2] + s[nt][3];
        }
        sA += __shfl_xor_sync(0xffffffffu, sA, 1);
        sA += __shfl_xor_sync(0xffffffffu, sA, 2);
        sB += __shfl_xor_sync(0xffffffffu, sB, 1);
        sB += __shfl_xor_sync(0xffffffffu, sB, 2);
        const float iAu = 1.0f / sA, iBu = 1.0f / sB;

        #pragma unroll
        for (int nt = 0; nt < 7; nt++) {
            int j0 = nt * 8 + ql * 2;
            if (vA) *(float2*)&SSM(rA, j0) = make_float2(s[nt][0] * iAu, s[nt][1] * iAu);
            if (vB) *(float2*)&SSM(rB, j0) = make_float2(s[nt][2] * iBu, s[nt][3] * iBu);
        }
    }
    // zero P pad cols 49..55 (rows 0..48) so ldmatrix reads are clean
    for (int idx = tid; idx < 49 * 7; idx += 128)
        SSM(idx / 7, 49 + idx % 7) = 0.f;
    __syncthreads();

    // coalesced attn write (fp32)
    float* aout = attn_out + (size_t)blk * PP * PP;
    for (int idx = tid; idx < PP * PP; idx += 128) {
        int r = idx / PP;
        aout[idx] = SSM(r, idx - r * PP);
    }

    // ---- O = P @ V ----
    int prow = wm + (lane & 15); if (prow > 48) prow = 48;
    const unsigned int paoff = (prow * 60 + 4 * (lane >> 4)) * 4;
    const unsigned int vboff = (((lane & 7) + 8 * (lane >> 4)) * 60
                                + 4 * ((lane >> 3) & 1)) * 4;

    float o[4][4];
    #pragma unroll
    for (int nt = 0; nt < 4; nt++)
        #pragma unroll
        for (int c = 0; c < 4; c++) o[nt][c] = 0.f;

    #pragma unroll
    for (int ks = 0; ks < 7; ks++) {
        const int k8 = ks * 8;
        unsigned int ar[4], a[4], b[4][2];
        ldsm4(ar[0], ar[1], ar[2], ar[3], usmB + paoff + k8 * 4);
        a[0] = f2tf32(__uint_as_float(ar[0]));
        a[1] = f2tf32(__uint_as_float(ar[1]));
        a[2] = f2tf32(__uint_as_float(ar[2]));
        a[3] = f2tf32(__uint_as_float(ar[3]));
        ldsm4(b[0][0], b[0][1], b[1][0], b[1][1], vsmB + vboff + k8 * 4);
        ldsm4(b[2][0], b[2][1], b[3][0], b[3][1], vsmB + vboff + (16 * 60 + k8) * 4);
        #pragma unroll
        for (int nt = 0; nt < 4; nt++)
            mma_tf32(o[nt], a[0], a[1], a[2], a[3], b[nt][0], b[nt][1]);
    }

    float* ob = g_omid + (size_t)win * PP * INNER + head * 32;
    #pragma unroll
    for (int nt = 0; nt < 4; nt++) {
        int c = nt * 8 + ql * 2;
        if (vA)
            *(float2*)&ob[(size_t)rA * INNER + c] =
                make_float2(tf32r(o[nt][0]), tf32r(o[nt][1]));
        if (vB)
            *(float2*)&ob[(size_t)rB * INNER + c] =
                make_float2(tf32r(o[nt][2]), tf32r(o[nt][3]));
    }
}

// ---------------------------------------------------------------------------
// Kernel 4: out GEMM, ldmatrix fragments, 3-stage cp.async, 512 thr,
// staged coalesced scatter. M=100352, N=128, K=256.
// A smem [m][k16] stride 20 at 0; B smem [n][k16] stride 20 at float 7680.
// ---------------------------------------------------------------------------
#define OSTG(r,c)   smbuf[(r) * 133 + (c)]

__global__ void __launch_bounds__(512, 2) out_gemm_tc(const float* __restrict__ b_out,
                                                      float* __restrict__ out)
{
    __shared__ float smbuf[17024];   // pipeline 15360 / staging 17024 union
    const unsigned int STG = 2560 * 4;

    const int tid  = threadIdx.x;
    const int bm   = blockIdx.y * 128;
    const int lane = tid & 31, wid = tid >> 5;
    const int wm   = (wid & 3) * 32, wn = (wid >> 2) * 32;
    const int qr   = lane >> 2, ql = lane & 3;

    const int fr = tid >> 2, fq = (tid & 3) * 4;
    const float* agp = g_omid   + (size_t)(bm + fr) * INNER + fq;
    const float* bgp = g_wout_r + (size_t)fr * 256 + fq;

    const unsigned int base = (unsigned int)__cvta_generic_to_shared(smbuf);
    const unsigned int aSm = base + (fr * 20 + fq) * 4;
    const unsigned int bSm = base + (7680 + fr * 20 + fq) * 4;

    // absolute ldmatrix addresses (FIX: base included on BOTH sides)
    const unsigned int aAbs = base + ((wm + (lane & 15)) * 20 + 4 * (lane >> 4)) * 4;
    const unsigned int bAbs = base + (7680 + ((lane & 7) + 8 * (lane >> 4) + wn) * 20
                                      + 4 * ((lane >> 3) & 1)) * 4;

    float acc[2][4][4];
    #pragma unroll
    for (int i = 0; i < 2; i++)
        #pragma unroll
        for (int j = 0; j < 4; j++)
            #pragma unroll
            for (int c = 0; c < 4; c++) acc[i][j][c] = 0.f;

    #pragma unroll
    for (int s = 0; s < 2; s++) {
        const int k0 = s * 16;
        cp16(aSm + s * STG, agp + k0);
        cp16(bSm + s * STG, bgp + k0);
        cp_commit();
    }

    #pragma unroll
    for (int ks = 0; ks < 16; ks++) {
        if (ks < 15) cp_wait1(); else cp_wait0();
        __syncthreads();
        const int st = ks % 3;
        #pragma unroll
        for (int k8 = 0; k8 < 16; k8 += 8) {
            unsigned int af[2][4], bf[4][2];
            ldsm4(af[0][0], af[0][1], af[0][2], af[0][3],
                  aAbs + st * STG + k8 * 4);
            ldsm4(af[1][0], af[1][1], af[1][2], af[1][3],
                  aAbs + st * STG + (320 + k8) * 4);
            ldsm4(bf[0][0], bf[0][1], bf[1][0], bf[1][1],
                  bAbs + st * STG + k8 * 4);
            ldsm4(bf[2][0], bf[2][1], bf[3][0], bf[3][1],
                  bAbs + st * STG + (320 + k8) * 4);
            #pragma unroll
            for (int mt = 0; mt < 2; mt++)
                #pragma unroll
                for (int nt = 0; nt < 4; nt++)
                    mma_tf32(acc[mt][nt], af[mt][0], af[mt][1], af[mt][2], af[mt][3],
                             bf[nt][0], bf[nt][1]);
        }
        __syncthreads();
        if (ks + 2 < 16) {
            const int snew = (ks + 2) % 3;
            const int k0 = (ks + 2) * 16;
            cp16(aSm + snew * STG, agp + k0);
            cp16(bSm + snew * STG, bgp + k0);
            cp_commit();
        }
    }

    __syncthreads();
    #pragma unroll
    for (int mt = 0; mt < 2; mt++) {
        #pragma unroll
        for (int half = 0; half < 2; half++) {
            int r = wm + mt * 16 + qr + half * 8;
            #pragma unroll
            for (int nt = 0; nt < 4; nt++) {
                int c = wn + nt * 8 + ql * 2;
                OSTG(r, c)     = acc[mt][nt][half * 2 + 0] + b_out[c];
                OSTG(r, c + 1) = acc[mt][nt][half * 2 + 1] + b_out[c + 1];
            }
        }
    }
    __syncthreads();

    for (int idx = tid; idx < 128 * 128; idx += 512) {
        int c  = idx >> 7;
        int sr = idx & 127;
        int r  = bm + sr;
        int win = r / PP;
        int t   = r - win * PP;
        int b   = win >> 6;
        int wl  = win & 63;
        int i1  = wl >> 3, i2 = wl & 7;
        int xx  = t / Pw,  yy = t - (t / Pw) * Pw;
        int h = i1 * Pw + xx + 3; if (h >= HW) h -= HW;
        int w = i2 * Pw + yy + 3; if (w >= HW) w -= HW;
        out[((size_t)b * 128 + c) * 3136 + h * HW + w] = OSTG(sr, c);
    }
}

// ---------------------------------------------------------------------------
extern "C" void kernel_launch(void* const* d_in, const int* in_sizes, int n_in,
                              void* d_out, int out_size)
{
    const float* x      = (const float*)d_in[0];
    const float* w_qkv  = (const float*)d_in[1];
    const float* w_out  = (const float*)d_in[2];
    const float* b_out  = (const float*)d_in[3];
    const float* pos    = (const float*)d_in[4];

    const long long O_ELEMS = (long long)Bb * Cc * HW * HW;
    const long long A_ELEMS = (long long)WINS * HEADS * PP * PP;

    float* outp = (float*)d_out;
    float* o_ptr;
    float* attn_ptr;

    if ((long long)out_size >= O_ELEMS + A_ELEMS) {
        o_ptr    = outp;
        attn_ptr = outp + O_ELEMS;
    } else if ((long long)out_size == A_ELEMS) {
        attn_ptr = outp;
        cudaGetSymbolAddress((void**)&o_ptr, g_o_dump);
    } else {
        o_ptr = outp;
        cudaGetSymbolAddress((void**)&attn_ptr, g_attn_dump);
    }

    prep_wm<<<512, 256>>>(w_qkv, w_out, pos);
    gather_x<<<Bb * 49, 256>>>(x);
    qkv_gemm_tc<<<dim3(768 / 128, MROWS / 128), 512>>>();
    attn_tc_kernel<<<WINS * HEADS, 128>>>(attn_ptr);
    out_gemm_tc<<<dim3(1, MROWS / 128), 512>>>(b_out, o_ptr);
}